// round 14
// baseline (speedup 1.0000x reference)
#include <cuda_runtime.h>

// Ende_3332894622093: B=65536, D=40, HB=20.
// out = [t1 | s2] (B,1,40);  J_T (B,40,40) =
//   [[diag(e4)+JJ12@J21, JJ12*e2], [J21, diag(e2)]]
// d_out: out flattened (n*40) then J_T flattened (n*1600).
//
// R14 = R12 body (k-outer fused D/E, jjt transposed staging, fused full-row
// stores with hoisted pointers, fast tanh/exp) with all always-true bounds
// guards removed (B % IPB == 0 exactly) and IPB=16 / (320,3) for 960 thr/SM.

#define IPB 16            // items per block (65536 % 16 == 0 -> no guards)
#define TPB (IPB * 20)    // 320 threads
#define WSS 624           // per-item smem stride (floats); 624 mod 32 = 16
#define XS  0
#define BB  40
#define S2  80
#define E2  100
#define E4  120
#define JJT 144
#define JST 24            // jjt row stride

__device__ __forceinline__ float tanh_fast(float x) {
    float r;
    asm("tanh.approx.f32 %0, %1;" : "=f"(r) : "f"(x));
    return r;
}

__global__ __launch_bounds__(TPB, 3)
void ende_kernel(const float* __restrict__ src,
                 const float* __restrict__ w1,
                 const float* __restrict__ w2,
                 const float* __restrict__ w3,
                 const float* __restrict__ w4,
                 float* __restrict__ outp,
                 float* __restrict__ jt)
{
    __shared__ float w1s[400], w2s[400], w3s[400], w4s[400];
    __shared__ __align__(16) float ws[IPB * WSS];

    const int tid = threadIdx.x;
    for (int i = tid; i < 400; i += TPB) {
        w1s[i] = w1[i];
        w2s[i] = w2[i];
        w3s[i] = w3[i];
        w4s[i] = w4[i];
    }

    const int itemL = tid / 20;
    const int j     = tid % 20;
    const int b     = blockIdx.x * IPB + itemL;
    float* S = &ws[itemL * WSS];

    // ---- cooperative x load (no bounds: grid covers B exactly) ----
    if (tid < IPB * 10) {
        int it = tid / 10, c = tid % 10;
        float4 v = ((const float4*)(src + (size_t)(blockIdx.x * IPB + it) * 40))[c];
        *(float4*)&ws[it * WSS + c * 4] = v;
    }
    __syncthreads();

    // ---- phase B: f1, f2, e2, (b1,b2), s2 ----
    float s2j;
    {
        float acc1 = 0.f, acc2 = 0.f;
        const float4* xv  = (const float4*)&S[XS];
        const float4* w1r = (const float4*)&w1s[j * 20];
        const float4* w2r = (const float4*)&w2s[j * 20];
        #pragma unroll
        for (int k4 = 0; k4 < 5; k4++) {
            float4 xx = xv[k4], a = w1r[k4], c = w2r[k4];
            acc1 += xx.x * a.x + xx.y * a.y + xx.z * a.z + xx.w * a.w;
            acc2 += xx.x * c.x + xx.y * c.y + xx.z * c.z + xx.w * c.w;
        }
        float f1 = tanh_fast(acc1);
        float f2 = tanh_fast(acc2);
        float e2 = __expf(f2);
        float p2  = S[XS + 20 + j];
        float p2e = p2 * e2;
        s2j = p2e + f1;
        ((float2*)&S[BB])[j] = make_float2(1.f - f1 * f1, p2e * (1.f - f2 * f2));
        S[S2 + j] = s2j;
        S[E2 + j] = e2;
    }
    __syncthreads();

    // ---- phase C: f3, f4, e4, t1, JJ12 row j -> jjt column (transposed) ----
    {
        float acc3 = 0.f, acc4 = 0.f;
        const float4* sv  = (const float4*)&S[S2];
        const float4* w3r = (const float4*)&w3s[j * 20];
        const float4* w4r = (const float4*)&w4s[j * 20];
        #pragma unroll
        for (int k4 = 0; k4 < 5; k4++) {
            float4 xx = sv[k4], a = w3r[k4], c = w4r[k4];
            acc3 += xx.x * a.x + xx.y * a.y + xx.z * a.z + xx.w * a.w;
            acc4 += xx.x * c.x + xx.y * c.y + xx.z * c.z + xx.w * c.w;
        }
        float f3 = tanh_fast(acc3);
        float f4 = tanh_fast(acc4);
        float e4 = __expf(f4);
        float s1  = S[XS + j];
        float s1e = s1 * e4;
        float a3 = 1.f - f3 * f3;
        float a4 = s1e * (1.f - f4 * f4);
        const int scol = j + (j >= 10 ? 2 : 0);   // pad slot at i=10,11
        #pragma unroll
        for (int k4 = 0; k4 < 5; k4++) {
            float4 a_ = w3r[k4], c_ = w4r[k4];
            S[JJT + (4 * k4 + 0) * JST + scol] = a3 * a_.x + a4 * c_.x;
            S[JJT + (4 * k4 + 1) * JST + scol] = a3 * a_.y + a4 * c_.y;
            S[JJT + (4 * k4 + 2) * JST + scol] = a3 * a_.z + a4 * c_.z;
            S[JJT + (4 * k4 + 3) * JST + scol] = a3 * a_.w + a4 * c_.w;
        }
        S[E4 + j] = e4;
        outp[(size_t)b * 40 + j]      = s1e + f3;  // t1
        outp[(size_t)b * 40 + 20 + j] = s2j;
    }
    __syncthreads();

    float* J = jt + (size_t)b * 1600;
    const int p    = j & 1;
    const int je   = j & ~1;
    const int ib12 = p * 12;          // jjt segment for own TL rows

    const float2 e2p = *(const float2*)&S[E2 + je];
    const float2 e4p = *(const float2*)&S[E4 + je];

    // Hoisted per-lane store pointers (loop-invariant; unrolled offsets -> imm)
    float* JA = J + 800 + (p ? 20 + je : je);        // rows 20..29: p0=BL, p1=BR
    float* JB = J + 800 + 400 + (p ? je : 20 + je);  // rows 30..39: p1=BL, p0=BR
    float* JT0 = J + (p ? 20 + je : je);             // rows 0..9:  p0=TL, p1=TR
    float* JT1 = J + 400 + (p ? je : 20 + je);       // rows 10..19: p1=TL, p0=TR

    // ---- fused D/E mainloop over k (one full-row store per k) ----
    float2 acc[10];
    #pragma unroll
    for (int ii = 0; ii < 10; ii++) acc[ii] = make_float2(0.f, 0.f);

    #pragma unroll
    for (int kk = 0; kk < 10; kk++) {
        float4 bbp = *(const float4*)&S[BB + 4 * kk];  // (b1,b2) for k=2kk,2kk+1
        #pragma unroll
        for (int s = 0; s < 2; s++) {
            const int k = 2 * kk + s;
            float b1v = s ? bbp.z : bbp.x;
            float b2v = s ? bbp.w : bbp.y;
            float2 wa = *(const float2*)&w1s[k * 20 + je];
            float2 wb = *(const float2*)&w2s[k * 20 + je];
            float2 mck = make_float2(b1v * wa.x + b2v * wb.x,
                                     b1v * wa.y + b2v * wb.y);
            // full row 20+k in ONE instruction: BL-owner lanes write mck,
            // other lanes write the BR diag pair; address is hoisted.
            {
                float2 br = make_float2(k == je ? e2p.x : 0.f,
                                        k == je + 1 ? e2p.y : 0.f);
                if (k < 10) {
                    float2 v = p ? br : mck;          // p0 owns BL rows 20..29
                    __stcs((float2*)&JA[k * 40], v);
                } else {
                    float2 v = p ? mck : br;          // p1 owns BL rows 30..39
                    __stcs((float2*)&JB[(k - 10) * 40], v);
                }
            }
            // accumulate TL rows: jjt[k][own segment]
            const float* jr = &S[JJT + k * JST + ib12];
            float4 ja = *(const float4*)jr;
            float4 jb = *(const float4*)(jr + 4);
            float2 jc = *(const float2*)(jr + 8);
            acc[0].x += ja.x * mck.x; acc[0].y += ja.x * mck.y;
            acc[1].x += ja.y * mck.x; acc[1].y += ja.y * mck.y;
            acc[2].x += ja.z * mck.x; acc[2].y += ja.z * mck.y;
            acc[3].x += ja.w * mck.x; acc[3].y += ja.w * mck.y;
            acc[4].x += jb.x * mck.x; acc[4].y += jb.x * mck.y;
            acc[5].x += jb.y * mck.x; acc[5].y += jb.y * mck.y;
            acc[6].x += jb.z * mck.x; acc[6].y += jb.z * mck.y;
            acc[7].x += jb.w * mck.x; acc[7].y += jb.w * mck.y;
            acc[8].x += jc.x * mck.x; acc[8].y += jc.x * mck.y;
            acc[9].x += jc.y * mck.x; acc[9].y += jc.y * mck.y;
        }
    }

    // ---- top epilogue: fused full rows, TR-flipped ----
    // Lane parity p: TL values are its acc rows (decade p); TR values it must
    // supply are rows of decade (1-p), read from the OTHER jjt segment.
    {
        const int ibT = (1 - p) * 12;
        const float* ra = &S[JJT + je * JST + ibT];
        const float* rb = &S[JJT + (je + 1) * JST + ibT];
        const int ibase = p * 10;
        #pragma unroll
        for (int ch = 0; ch < 3; ch++) {
            const int i0 = ch * 4;
            const int cnt = (ch == 2) ? 2 : 4;
            float av[4], bv[4];
            if (ch < 2) {
                float4 a = *(const float4*)(ra + i0);
                float4 bq = *(const float4*)(rb + i0);
                av[0]=a.x; av[1]=a.y; av[2]=a.z; av[3]=a.w;
                bv[0]=bq.x; bv[1]=bq.y; bv[2]=bq.z; bv[3]=bq.w;
            } else {
                float2 a = *(const float2*)(ra + i0);
                float2 bq = *(const float2*)(rb + i0);
                av[0]=a.x; av[1]=a.y; bv[0]=bq.x; bv[1]=bq.y;
            }
            #pragma unroll
            for (int t = 0; t < 4; t++) {
                if (t >= cnt) break;
                const int ii = i0 + t;
                // TL for own row ibase+ii (with diagonal)
                float2 tl = acc[ii];
                {
                    int i = ibase + ii;
                    if (i == je)     tl.x += e4p.x;
                    if (i == je + 1) tl.y += e4p.y;
                }
                // TR for other-decade row (1-p)*10 + ii
                float2 tr = make_float2(av[t] * e2p.x, bv[t] * e2p.y);
                // row ii (decade 0): p0 -> TL, p1 -> TR
                float2 v0 = p ? tr : tl;
                __stcs((float2*)&JT0[ii * 40], v0);
                // row 10+ii (decade 1): p1 -> TL, p0 -> TR
                float2 v1 = p ? tl : tr;
                __stcs((float2*)&JT1[ii * 40], v1);
            }
        }
    }
}

extern "C" void kernel_launch(void* const* d_in, const int* in_sizes, int n_in,
                              void* d_out, int out_size)
{
    const float* src = (const float*)d_in[0];
    const float* w1  = (const float*)d_in[1];
    const float* w2  = (const float*)d_in[2];
    const float* w3  = (const float*)d_in[3];
    const float* w4  = (const float*)d_in[4];

    int n = in_sizes[0] / 40;
    float* outp = (float*)d_out;
    float* jt   = (float*)d_out + (size_t)n * 40;

    int blocks = n / IPB;   // B = 65536 divisible by IPB = 16
    ende_kernel<<<blocks, TPB>>>(src, w1, w2, w3, w4, outp, jt);
}

// round 16
// speedup vs baseline: 1.0686x; 1.0686x over previous
#include <cuda_runtime.h>

// Ende_3332894622093: B=65536, D=40, HB=20.
// out = [t1 | s2] (B,1,40);  J_T (B,40,40) =
//   [[diag(e4)+JJ12@J21, JJ12*e2], [J21, diag(e2)]]
// d_out: out flattened (n*40) then J_T flattened (n*1600).
//
// R16 = R15 (J21 produced in phase B while the w1/w2 row is hot, staged
// row-major; mainloop mck = ONE LDS.64) with the smem layout overlap fixed:
// E4 occupies [80,100); J21S starts at 100; JJT at 504.

#define IPB 8             // items per block (65536 % 8 == 0 -> no guards)
#define TPB (IPB * 20)    // 160 threads
#define WSS 1008          // per-item smem stride (floats); 1008 mod 32 = 16
#define XS   0
#define S2   40
#define E2   60
#define E4   80           // [80,100)
#define J21S 100          // 20 rows x 20 floats, row-major  [100,500)
#define JJT  504          // 20 rows x 24 floats (transposed JJ12, pad @10,11) [504,984)
#define JST  24

__device__ __forceinline__ float tanh_fast(float x) {
    float r;
    asm("tanh.approx.f32 %0, %1;" : "=f"(r) : "f"(x));
    return r;
}

__global__ __launch_bounds__(TPB, 5)
void ende_kernel(const float* __restrict__ src,
                 const float* __restrict__ w1,
                 const float* __restrict__ w2,
                 const float* __restrict__ w3,
                 const float* __restrict__ w4,
                 float* __restrict__ outp,
                 float* __restrict__ jt)
{
    __shared__ float w1s[400], w2s[400], w3s[400], w4s[400];
    __shared__ __align__(16) float ws[IPB * WSS];

    const int tid = threadIdx.x;
    for (int i = tid; i < 400; i += TPB) {
        w1s[i] = w1[i];
        w2s[i] = w2[i];
        w3s[i] = w3[i];
        w4s[i] = w4[i];
    }

    const int itemL = tid / 20;
    const int j     = tid % 20;
    const int b     = blockIdx.x * IPB + itemL;
    float* S = &ws[itemL * WSS];

    // ---- cooperative x load (grid covers B exactly) ----
    if (tid < IPB * 10) {
        int it = tid / 10, c = tid % 10;
        float4 v = ((const float4*)(src + (size_t)(blockIdx.x * IPB + it) * 40))[c];
        *(float4*)&ws[it * WSS + c * 4] = v;
    }
    __syncthreads();

    // ---- phase B: f1, f2, e2, s2, and J21 row j (staged row-major) ----
    float s2j;
    {
        float acc1 = 0.f, acc2 = 0.f;
        const float4* xv  = (const float4*)&S[XS];
        const float4* w1r = (const float4*)&w1s[j * 20];
        const float4* w2r = (const float4*)&w2s[j * 20];
        #pragma unroll
        for (int k4 = 0; k4 < 5; k4++) {
            float4 xx = xv[k4], a = w1r[k4], c = w2r[k4];
            acc1 += xx.x * a.x + xx.y * a.y + xx.z * a.z + xx.w * a.w;
            acc2 += xx.x * c.x + xx.y * c.y + xx.z * c.z + xx.w * c.w;
        }
        float f1 = tanh_fast(acc1);
        float f2 = tanh_fast(acc2);
        float e2 = __expf(f2);
        float p2  = S[XS + 20 + j];
        float p2e = p2 * e2;
        s2j = p2e + f1;
        float b1 = 1.f - f1 * f1;
        float b2 = p2e * (1.f - f2 * f2);
        // J21 row j = b1*w1[j][:] + b2*w2[j][:]  (w rows are hot)
        float4* dst = (float4*)&S[J21S + j * 20];
        #pragma unroll
        for (int k4 = 0; k4 < 5; k4++) {
            float4 a = w1r[k4], c = w2r[k4], r;
            r.x = b1 * a.x + b2 * c.x;
            r.y = b1 * a.y + b2 * c.y;
            r.z = b1 * a.z + b2 * c.z;
            r.w = b1 * a.w + b2 * c.w;
            dst[k4] = r;
        }
        S[S2 + j] = s2j;
        S[E2 + j] = e2;
    }
    __syncthreads();

    // ---- phase C: f3, f4, e4, t1, JJ12 row j -> jjt column (transposed) ----
    {
        float acc3 = 0.f, acc4 = 0.f;
        const float4* sv  = (const float4*)&S[S2];
        const float4* w3r = (const float4*)&w3s[j * 20];
        const float4* w4r = (const float4*)&w4s[j * 20];
        #pragma unroll
        for (int k4 = 0; k4 < 5; k4++) {
            float4 xx = sv[k4], a = w3r[k4], c = w4r[k4];
            acc3 += xx.x * a.x + xx.y * a.y + xx.z * a.z + xx.w * a.w;
            acc4 += xx.x * c.x + xx.y * c.y + xx.z * c.z + xx.w * c.w;
        }
        float f3 = tanh_fast(acc3);
        float f4 = tanh_fast(acc4);
        float e4 = __expf(f4);
        float s1  = S[XS + j];
        float s1e = s1 * e4;
        float a3 = 1.f - f3 * f3;
        float a4 = s1e * (1.f - f4 * f4);
        const int scol = j + (j >= 10 ? 2 : 0);   // pad slot at i=10,11
        #pragma unroll
        for (int k4 = 0; k4 < 5; k4++) {
            float4 a_ = w3r[k4], c_ = w4r[k4];
            S[JJT + (4 * k4 + 0) * JST + scol] = a3 * a_.x + a4 * c_.x;
            S[JJT + (4 * k4 + 1) * JST + scol] = a3 * a_.y + a4 * c_.y;
            S[JJT + (4 * k4 + 2) * JST + scol] = a3 * a_.z + a4 * c_.z;
            S[JJT + (4 * k4 + 3) * JST + scol] = a3 * a_.w + a4 * c_.w;
        }
        S[E4 + j] = e4;
        outp[(size_t)b * 40 + j]      = s1e + f3;  // t1
        outp[(size_t)b * 40 + 20 + j] = s2j;
    }
    __syncthreads();

    float* J = jt + (size_t)b * 1600;
    const int p    = j & 1;
    const int je   = j & ~1;
    const int ib12 = p * 12;          // jjt segment for own TL rows

    const float2 e2p = *(const float2*)&S[E2 + je];
    const float2 e4p = *(const float2*)&S[E4 + je];

    // Hoisted per-lane store pointers (loop-invariant; unrolled offsets -> imm)
    float* JA = J + 800 + (p ? 20 + je : je);        // rows 20..29: p0=BL, p1=BR
    float* JB = J + 800 + 400 + (p ? je : 20 + je);  // rows 30..39: p1=BL, p0=BR
    float* JT0 = J + (p ? 20 + je : je);             // rows 0..9:  p0=TL, p1=TR
    float* JT1 = J + 400 + (p ? je : 20 + je);       // rows 10..19: p1=TL, p0=TR

    // ---- fused D/E mainloop over k (1 LDS.64 + 3 jjt LDS + 1 store per k) ----
    float2 acc[10];
    #pragma unroll
    for (int ii = 0; ii < 10; ii++) acc[ii] = make_float2(0.f, 0.f);

    #pragma unroll
    for (int k = 0; k < 20; k++) {
        float2 mck = *(const float2*)&S[J21S + k * 20 + je];
        // full row 20+k in ONE instruction: BL-owner lanes write mck,
        // other lanes write the BR diag pair; address is hoisted.
        {
            float2 br = make_float2(k == je ? e2p.x : 0.f,
                                    k == je + 1 ? e2p.y : 0.f);
            if (k < 10) {
                float2 v = p ? br : mck;          // p0 owns BL rows 20..29
                __stcs((float2*)&JA[k * 40], v);
            } else {
                float2 v = p ? mck : br;          // p1 owns BL rows 30..39
                __stcs((float2*)&JB[(k - 10) * 40], v);
            }
        }
        // accumulate TL rows: jjt[k][own segment]
        const float* jr = &S[JJT + k * JST + ib12];
        float4 ja = *(const float4*)jr;
        float4 jb = *(const float4*)(jr + 4);
        float2 jc = *(const float2*)(jr + 8);
        acc[0].x += ja.x * mck.x; acc[0].y += ja.x * mck.y;
        acc[1].x += ja.y * mck.x; acc[1].y += ja.y * mck.y;
        acc[2].x += ja.z * mck.x; acc[2].y += ja.z * mck.y;
        acc[3].x += ja.w * mck.x; acc[3].y += ja.w * mck.y;
        acc[4].x += jb.x * mck.x; acc[4].y += jb.x * mck.y;
        acc[5].x += jb.y * mck.x; acc[5].y += jb.y * mck.y;
        acc[6].x += jb.z * mck.x; acc[6].y += jb.z * mck.y;
        acc[7].x += jb.w * mck.x; acc[7].y += jb.w * mck.y;
        acc[8].x += jc.x * mck.x; acc[8].y += jc.x * mck.y;
        acc[9].x += jc.y * mck.x; acc[9].y += jc.y * mck.y;
    }

    // ---- top epilogue: fused full rows, TR-flipped (unchanged from R12) ----
    {
        const int ibT = (1 - p) * 12;
        const float* ra = &S[JJT + je * JST + ibT];
        const float* rb = &S[JJT + (je + 1) * JST + ibT];
        const int ibase = p * 10;
        #pragma unroll
        for (int ch = 0; ch < 3; ch++) {
            const int i0 = ch * 4;
            const int cnt = (ch == 2) ? 2 : 4;
            float av[4], bv[4];
            if (ch < 2) {
                float4 a = *(const float4*)(ra + i0);
                float4 bq = *(const float4*)(rb + i0);
                av[0]=a.x; av[1]=a.y; av[2]=a.z; av[3]=a.w;
                bv[0]=bq.x; bv[1]=bq.y; bv[2]=bq.z; bv[3]=bq.w;
            } else {
                float2 a = *(const float2*)(ra + i0);
                float2 bq = *(const float2*)(rb + i0);
                av[0]=a.x; av[1]=a.y; bv[0]=bq.x; bv[1]=bq.y;
            }
            #pragma unroll
            for (int t = 0; t < 4; t++) {
                if (t >= cnt) break;
                const int ii = i0 + t;
                float2 tl = acc[ii];
                {
                    int i = ibase + ii;
                    if (i == je)     tl.x += e4p.x;
                    if (i == je + 1) tl.y += e4p.y;
                }
                float2 tr = make_float2(av[t] * e2p.x, bv[t] * e2p.y);
                float2 v0 = p ? tr : tl;
                __stcs((float2*)&JT0[ii * 40], v0);
                float2 v1 = p ? tl : tr;
                __stcs((float2*)&JT1[ii * 40], v1);
            }
        }
    }
}

extern "C" void kernel_launch(void* const* d_in, const int* in_sizes, int n_in,
                              void* d_out, int out_size)
{
    const float* src = (const float*)d_in[0];
    const float* w1  = (const float*)d_in[1];
    const float* w2  = (const float*)d_in[2];
    const float* w3  = (const float*)d_in[3];
    const float* w4  = (const float*)d_in[4];

    int n = in_sizes[0] / 40;
    float* outp = (float*)d_out;
    float* jt   = (float*)d_out + (size_t)n * 40;

    int blocks = n / IPB;   // B = 65536 divisible by IPB = 8
    ende_kernel<<<blocks, TPB>>>(src, w1, w2, w3, w4, outp, jt);
}